// round 2
// baseline (speedup 1.0000x reference)
#include <cuda_runtime.h>
#include <cuda_fp16.h>
#include <cstdint>

// ============================================================
// Problem dims (fixed)
// ============================================================
#define MDIM 8192     // B*S
#define NDIM 4096
#define KDIM 4096
#define NGROUPS 64    // group size 64

// Scratch: half-precision copies (sanctioned __device__ globals)
__device__ __half g_Wh[(size_t)NDIM * KDIM];   // 32 MB
__device__ __half g_Xh[(size_t)MDIM * KDIM];   // 64 MB

// ============================================================
// Pass 1: dequantize W (int32 codes 0..3) -> half
// ============================================================
__global__ void __launch_bounds__(256) dequant_kernel(
    const int* __restrict__ q, const float* __restrict__ scale, const float* __restrict__ zp)
{
    int idx = blockIdx.x * 256 + threadIdx.x;            // 8 elements per thread
    int n = idx >> 9;                                    // K/8 = 512 per row
    int k = (idx & 511) << 3;
    int g = k >> 6;
    float s = scale[n * NGROUPS + g];
    float z = zp[n * NGROUPS + g];
    int4 q0 = reinterpret_cast<const int4*>(q)[idx * 2 + 0];
    int4 q1 = reinterpret_cast<const int4*>(q)[idx * 2 + 1];
    __half2 h[4];
    h[0] = __floats2half2_rn(((float)q0.x - z) * s, ((float)q0.y - z) * s);
    h[1] = __floats2half2_rn(((float)q0.z - z) * s, ((float)q0.w - z) * s);
    h[2] = __floats2half2_rn(((float)q1.x - z) * s, ((float)q1.y - z) * s);
    h[3] = __floats2half2_rn(((float)q1.z - z) * s, ((float)q1.w - z) * s);
    reinterpret_cast<uint4*>(g_Wh)[idx] = *reinterpret_cast<uint4*>(h);
}

// ============================================================
// Pass 2: x fp32 -> half
// ============================================================
__global__ void __launch_bounds__(256) xconv_kernel(const float* __restrict__ x)
{
    int idx = blockIdx.x * 256 + threadIdx.x;            // 8 floats per thread
    float4 a = reinterpret_cast<const float4*>(x)[idx * 2 + 0];
    float4 b = reinterpret_cast<const float4*>(x)[idx * 2 + 1];
    __half2 h[4];
    h[0] = __floats2half2_rn(a.x, a.y);
    h[1] = __floats2half2_rn(a.z, a.w);
    h[2] = __floats2half2_rn(b.x, b.y);
    h[3] = __floats2half2_rn(b.z, b.w);
    reinterpret_cast<uint4*>(g_Xh)[idx] = *reinterpret_cast<uint4*>(h);
}

// ============================================================
// Pass 3: GEMM  out[M,N] = Xh @ Wh^T + bias   (fp16 in, fp32 acc)
// CTA tile 256x128, 8 warps (warp 64x64), K-stage = 64 halves, 3 stages
// ============================================================
constexpr int TILE_M = 256;
constexpr int TILE_N = 128;
constexpr int KS = 64;                          // halves per stage (128 B per row)
constexpr int NSTAGE = 3;
constexpr int NKS = KDIM / KS;                  // 64 stages of K
constexpr int A_STAGE_B = TILE_M * 128;         // 32 KB
constexpr int B_STAGE_B = TILE_N * 128;         // 16 KB
constexpr int STAGE_B = A_STAGE_B + B_STAGE_B;  // 48 KB
constexpr int SMEM_BYTES = NSTAGE * STAGE_B;    // 144 KB

__device__ __forceinline__ uint32_t smem_u32(const void* p) {
    uint32_t a;
    asm("{ .reg .u64 t; cvta.to.shared.u64 t, %1; cvt.u32.u64 %0, t; }" : "=r"(a) : "l"(p));
    return a;
}
__device__ __forceinline__ void cp_async16(uint32_t dst, const void* src) {
    asm volatile("cp.async.cg.shared.global [%0], [%1], 16;" :: "r"(dst), "l"(src));
}
__device__ __forceinline__ void cp_commit() {
    asm volatile("cp.async.commit_group;" ::: "memory");
}
template <int N>
__device__ __forceinline__ void cp_wait() {
    asm volatile("cp.async.wait_group %0;" :: "n"(N) : "memory");
}
__device__ __forceinline__ void ldmatrix_x4(uint32_t& r0, uint32_t& r1, uint32_t& r2, uint32_t& r3,
                                            uint32_t addr) {
    asm volatile("ldmatrix.sync.aligned.m8n8.x4.shared.b16 {%0,%1,%2,%3}, [%4];"
                 : "=r"(r0), "=r"(r1), "=r"(r2), "=r"(r3) : "r"(addr));
}
__device__ __forceinline__ void mma16816(float* c, uint32_t a0, uint32_t a1, uint32_t a2, uint32_t a3,
                                         uint32_t b0, uint32_t b1) {
    asm volatile(
        "mma.sync.aligned.m16n8k16.row.col.f32.f16.f16.f32 "
        "{%0,%1,%2,%3}, {%4,%5,%6,%7}, {%8,%9}, {%0,%1,%2,%3};"
        : "+f"(c[0]), "+f"(c[1]), "+f"(c[2]), "+f"(c[3])
        : "r"(a0), "r"(a1), "r"(a2), "r"(a3), "r"(b0), "r"(b1));
}

__global__ void __launch_bounds__(256, 1) gemm_kernel(
    const float* __restrict__ bias, float* __restrict__ out)
{
    extern __shared__ __align__(1024) char smem[];
    const uint32_t sb = smem_u32(smem);
    const int tid = threadIdx.x;
    const int wid = tid >> 5;
    const int lane = tid & 31;

    const int m_base = blockIdx.y * TILE_M;
    const int n_base = blockIdx.x * TILE_N;
    const int warp_m = (wid >> 1) * 64;   // 4 warps along M
    const int warp_n = (wid & 1) * 64;    // 2 warps along N

    // ---------- cp.async source/dst precompute ----------
    // A: thread t loads row t (all 8 chunks). B: row t&127, chunks (t>>7)*4 .. +3
    const __half* gA = g_Xh + (size_t)(m_base + tid) * KDIM;
    const int browb = tid & 127;
    const int bcs = (tid >> 7) * 4;
    const __half* gB = g_Wh + (size_t)(n_base + browb) * KDIM + bcs * 8;

    uint32_t aDst[8], bDst[4];
    #pragma unroll
    for (int c = 0; c < 8; c++)
        aDst[c] = (uint32_t)(tid * 128 + ((c ^ (tid & 7)) * 16));
    #pragma unroll
    for (int c = 0; c < 4; c++)
        bDst[c] = (uint32_t)(A_STAGE_B + browb * 128 + (((bcs + c) ^ (browb & 7)) * 16));

    auto issue_stage = [&](int ks, int stage) {
        uint32_t base = sb + stage * STAGE_B;
        const __half* a = gA + ks * KS;
        const __half* b = gB + ks * KS;
        #pragma unroll
        for (int c = 0; c < 8; c++) cp_async16(base + aDst[c], a + c * 8);
        #pragma unroll
        for (int c = 0; c < 4; c++) cp_async16(base + bDst[c], b + c * 8);
    };

    // ---------- prologue: 2 stages in flight ----------
    issue_stage(0, 0); cp_commit();
    issue_stage(1, 1); cp_commit();

    float acc[4][8][4];
    #pragma unroll
    for (int i = 0; i < 4; i++)
        #pragma unroll
        for (int j = 0; j < 8; j++)
            #pragma unroll
            for (int r = 0; r < 4; r++) acc[i][j][r] = 0.f;

    // ldmatrix lane addressing (within-tile), shared by A and B
    const int lrow = lane & 15;          // row within 16-row tile
    const int lhc = lane >> 4;           // hi/lo 16B chunk of the k16
    const int lsw = lrow & 7;            // swizzle XOR term

    int stage = 0;
    for (int ks = 0; ks < NKS; ks++) {
        cp_wait<1>();
        __syncthreads();
        if (ks + 2 < NKS) issue_stage(ks + 2, (stage + 2) % NSTAGE);
        cp_commit();

        const uint32_t abase = sb + stage * STAGE_B;
        const uint32_t bbase = abase + A_STAGE_B;

        #pragma unroll
        for (int kk = 0; kk < 4; kk++) {           // 4 x k16 per stage
            const int chunk = 2 * kk + lhc;
            uint32_t af[4][4], bf[4][4];
            #pragma unroll
            for (int i = 0; i < 4; i++) {          // A: 4 m16 tiles
                int row = warp_m + i * 16 + lrow;
                uint32_t addr = abase + row * 128 + ((chunk ^ lsw) * 16);
                ldmatrix_x4(af[i][0], af[i][1], af[i][2], af[i][3], addr);
            }
            #pragma unroll
            for (int jj = 0; jj < 4; jj++) {       // B: 4 n16 tiles
                int row = warp_n + jj * 16 + lrow;
                uint32_t addr = bbase + row * 128 + ((chunk ^ lsw) * 16);
                ldmatrix_x4(bf[jj][0], bf[jj][1], bf[jj][2], bf[jj][3], addr);
            }
            #pragma unroll
            for (int i = 0; i < 4; i++)
                #pragma unroll
                for (int jj = 0; jj < 4; jj++) {
                    mma16816(acc[i][jj * 2 + 0], af[i][0], af[i][1], af[i][2], af[i][3],
                             bf[jj][0], bf[jj][2]);
                    mma16816(acc[i][jj * 2 + 1], af[i][0], af[i][1], af[i][2], af[i][3],
                             bf[jj][1], bf[jj][3]);
                }
        }
        stage = (stage + 1) % NSTAGE;
    }

    // ---------- epilogue: bias + store (float2 per fragment row) ----------
    const int qm = lane >> 2;            // 0..7
    const int qn = (lane & 3) * 2;       // 0,2,4,6
    #pragma unroll
    for (int j = 0; j < 8; j++) {
        int n0 = n_base + warp_n + j * 8 + qn;
        float2 bv = *reinterpret_cast<const float2*>(bias + n0);
        #pragma unroll
        for (int i = 0; i < 4; i++) {
            int m0 = m_base + warp_m + i * 16 + qm;
            float2 v0 = { acc[i][j][0] + bv.x, acc[i][j][1] + bv.y };
            float2 v1 = { acc[i][j][2] + bv.x, acc[i][j][3] + bv.y };
            *reinterpret_cast<float2*>(out + (size_t)m0 * NDIM + n0) = v0;
            *reinterpret_cast<float2*>(out + (size_t)(m0 + 8) * NDIM + n0) = v1;
        }
    }
}

// ============================================================
// Launch
// ============================================================
extern "C" void kernel_launch(void* const* d_in, const int* in_sizes, int n_in,
                              void* d_out, int out_size) {
    const float* x     = (const float*)d_in[0];
    const int*   wq    = (const int*)d_in[1];
    const float* scale = (const float*)d_in[2];
    const float* zp    = (const float*)d_in[3];
    const float* bias  = (const float*)d_in[4];
    float* out = (float*)d_out;

    dequant_kernel<<<(size_t)NDIM * KDIM / 8 / 256, 256>>>(wq, scale, zp);
    xconv_kernel<<<(size_t)MDIM * KDIM / 8 / 256, 256>>>(x);

    static bool attr_set = false;
    if (!attr_set) {
        cudaFuncSetAttribute(gemm_kernel, cudaFuncAttributeMaxDynamicSharedMemorySize, SMEM_BYTES);
        attr_set = true;
    }
    dim3 grid(NDIM / TILE_N, MDIM / TILE_M);   // (32, 32)
    gemm_kernel<<<grid, 256, SMEM_BYTES>>>(bias, out);
}

// round 3
// speedup vs baseline: 1.3430x; 1.3430x over previous
#include <cuda_runtime.h>
#include <cuda_fp16.h>
#include <cstdint>

// ============================================================
// Problem dims (fixed)
// ============================================================
#define MDIM 8192     // B*S
#define NDIM 4096
#define KDIM 4096
#define NGROUPS 64    // group size 64

// Scratch: half-precision copies (sanctioned __device__ globals)
__device__ __half g_Wh[(size_t)NDIM * KDIM];   // 32 MB
__device__ __half g_Xh[(size_t)MDIM * KDIM];   // 64 MB

// ============================================================
// Pass 1: dequantize W (int32 codes 0..3) -> half
// ============================================================
__global__ void __launch_bounds__(256) dequant_kernel(
    const int* __restrict__ q, const float* __restrict__ scale, const float* __restrict__ zp)
{
    int idx = blockIdx.x * 256 + threadIdx.x;            // 8 elements per thread
    int n = idx >> 9;                                    // K/8 = 512 per row
    int k = (idx & 511) << 3;
    int g = k >> 6;
    float s = scale[n * NGROUPS + g];
    float z = zp[n * NGROUPS + g];
    int4 q0 = reinterpret_cast<const int4*>(q)[idx * 2 + 0];
    int4 q1 = reinterpret_cast<const int4*>(q)[idx * 2 + 1];
    __half2 h[4];
    h[0] = __floats2half2_rn(((float)q0.x - z) * s, ((float)q0.y - z) * s);
    h[1] = __floats2half2_rn(((float)q0.z - z) * s, ((float)q0.w - z) * s);
    h[2] = __floats2half2_rn(((float)q1.x - z) * s, ((float)q1.y - z) * s);
    h[3] = __floats2half2_rn(((float)q1.z - z) * s, ((float)q1.w - z) * s);
    reinterpret_cast<uint4*>(g_Wh)[idx] = *reinterpret_cast<uint4*>(h);
}

// ============================================================
// Pass 2: x fp32 -> half
// ============================================================
__global__ void __launch_bounds__(256) xconv_kernel(const float* __restrict__ x)
{
    int idx = blockIdx.x * 256 + threadIdx.x;            // 8 floats per thread
    float4 a = reinterpret_cast<const float4*>(x)[idx * 2 + 0];
    float4 b = reinterpret_cast<const float4*>(x)[idx * 2 + 1];
    __half2 h[4];
    h[0] = __floats2half2_rn(a.x, a.y);
    h[1] = __floats2half2_rn(a.z, a.w);
    h[2] = __floats2half2_rn(b.x, b.y);
    h[3] = __floats2half2_rn(b.z, b.w);
    reinterpret_cast<uint4*>(g_Xh)[idx] = *reinterpret_cast<uint4*>(h);
}

// ============================================================
// Pass 3: GEMM  out[M,N] = Xh @ Wh^T + bias   (fp16 in, fp32 acc)
// CTA tile 128x128, 8 warps (warp 64x32, grid 2Mx4N), KS=64, 3 stages
// 96 KB smem  ->  2 CTAs/SM (4 warps/SMSP) for latency hiding.
// Fragments double-buffered in registers: LDSM(kk+1) issued before MMA(kk).
// ============================================================
constexpr int TILE_M = 128;
constexpr int TILE_N = 128;
constexpr int KS = 64;                          // halves per stage (128 B per row)
constexpr int NSTAGE = 3;
constexpr int NKS = KDIM / KS;                  // 64 K-stages
constexpr int A_STAGE_B = TILE_M * 128;         // 16 KB
constexpr int B_STAGE_B = TILE_N * 128;         // 16 KB
constexpr int STAGE_B = A_STAGE_B + B_STAGE_B;  // 32 KB
constexpr int SMEM_BYTES = NSTAGE * STAGE_B;    // 96 KB

__device__ __forceinline__ uint32_t smem_u32(const void* p) {
    uint32_t a;
    asm("{ .reg .u64 t; cvta.to.shared.u64 t, %1; cvt.u32.u64 %0, t; }" : "=r"(a) : "l"(p));
    return a;
}
__device__ __forceinline__ void cp_async16(uint32_t dst, const void* src) {
    asm volatile("cp.async.cg.shared.global [%0], [%1], 16;" :: "r"(dst), "l"(src));
}
__device__ __forceinline__ void cp_commit() {
    asm volatile("cp.async.commit_group;" ::: "memory");
}
template <int N>
__device__ __forceinline__ void cp_wait() {
    asm volatile("cp.async.wait_group %0;" :: "n"(N) : "memory");
}
__device__ __forceinline__ void ldmatrix_x4(uint32_t& r0, uint32_t& r1, uint32_t& r2, uint32_t& r3,
                                            uint32_t addr) {
    asm volatile("ldmatrix.sync.aligned.m8n8.x4.shared.b16 {%0,%1,%2,%3}, [%4];"
                 : "=r"(r0), "=r"(r1), "=r"(r2), "=r"(r3) : "r"(addr));
}
__device__ __forceinline__ void mma16816(float* c, const uint32_t* a, uint32_t b0, uint32_t b1) {
    asm volatile(
        "mma.sync.aligned.m16n8k16.row.col.f32.f16.f16.f32 "
        "{%0,%1,%2,%3}, {%4,%5,%6,%7}, {%8,%9}, {%0,%1,%2,%3};"
        : "+f"(c[0]), "+f"(c[1]), "+f"(c[2]), "+f"(c[3])
        : "r"(a[0]), "r"(a[1]), "r"(a[2]), "r"(a[3]), "r"(b0), "r"(b1));
}

__global__ void __launch_bounds__(256, 2) gemm_kernel(
    const float* __restrict__ bias, float* __restrict__ out)
{
    extern __shared__ __align__(1024) char smem[];
    const uint32_t sb = smem_u32(smem);
    const int tid = threadIdx.x;
    const int wid = tid >> 5;
    const int lane = tid & 31;

    const int m_base = blockIdx.y * TILE_M;
    const int n_base = blockIdx.x * TILE_N;
    const int warp_m = (wid >> 2) * 64;   // 2 warps along M
    const int warp_n = (wid & 3) * 32;    // 4 warps along N

    // ---------- cp.async addressing ----------
    // 128 rows x 8 chunks(16B) per operand; 256 threads -> 4 chunks each.
    const int row = tid >> 1;
    const int cs = (tid & 1) * 4;
    const __half* gA = g_Xh + (size_t)(m_base + row) * KDIM + cs * 8;
    const __half* gB = g_Wh + (size_t)(n_base + row) * KDIM + cs * 8;

    uint32_t aDst[4], bDst[4];
    #pragma unroll
    for (int c = 0; c < 4; c++) {
        uint32_t off = row * 128 + (((cs + c) ^ (row & 7)) * 16);
        aDst[c] = off;
        bDst[c] = A_STAGE_B + off;
    }

    auto issue_stage = [&](int ks, int stage) {
        uint32_t base = sb + stage * STAGE_B;
        const __half* a = gA + ks * KS;
        const __half* b = gB + ks * KS;
        #pragma unroll
        for (int c = 0; c < 4; c++) cp_async16(base + aDst[c], a + c * 8);
        #pragma unroll
        for (int c = 0; c < 4; c++) cp_async16(base + bDst[c], b + c * 8);
    };

    issue_stage(0, 0); cp_commit();
    issue_stage(1, 1); cp_commit();

    float acc[4][4][4];
    #pragma unroll
    for (int i = 0; i < 4; i++)
        #pragma unroll
        for (int j = 0; j < 4; j++)
            #pragma unroll
            for (int r = 0; r < 4; r++) acc[i][j][r] = 0.f;

    // ldmatrix lane addressing
    const int lrow = lane & 15;
    const int lhc = lane >> 4;           // hi/lo 16B chunk within k16
    const int lsw = lrow & 7;

    // Per-kk fragment loader (A: 4 m16 tiles, B: 2 n16 tiles)
    uint32_t af[2][4][4], bf[2][2][4];   // double-buffered
    auto load_frags = [&](int kk, uint32_t abase, uint32_t bbase, int buf) {
        const int chunk = 2 * kk + lhc;
        const uint32_t coff = (uint32_t)((chunk ^ lsw) * 16);
        #pragma unroll
        for (int i = 0; i < 4; i++) {
            uint32_t addr = abase + (warp_m + i * 16 + lrow) * 128 + coff;
            ldmatrix_x4(af[buf][i][0], af[buf][i][1], af[buf][i][2], af[buf][i][3], addr);
        }
        #pragma unroll
        for (int j = 0; j < 2; j++) {
            uint32_t addr = bbase + (warp_n + j * 16 + lrow) * 128 + coff;
            ldmatrix_x4(bf[buf][j][0], bf[buf][j][1], bf[buf][j][2], bf[buf][j][3], addr);
        }
    };
    auto do_mma = [&](int buf) {
        #pragma unroll
        for (int i = 0; i < 4; i++)
            #pragma unroll
            for (int j = 0; j < 2; j++) {
                mma16816(acc[i][j * 2 + 0], af[buf][i], bf[buf][j][0], bf[buf][j][2]);
                mma16816(acc[i][j * 2 + 1], af[buf][i], bf[buf][j][1], bf[buf][j][3]);
            }
    };

    int stage = 0;
    for (int ks = 0; ks < NKS; ks++) {
        cp_wait<1>();
        __syncthreads();
        if (ks + 2 < NKS) issue_stage(ks + 2, (stage + 2 >= NSTAGE) ? stage + 2 - NSTAGE : stage + 2);
        cp_commit();

        const uint32_t abase = sb + stage * STAGE_B;
        const uint32_t bbase = abase + A_STAGE_B;

        // software-pipelined: LDSM(kk+1) before MMA(kk)
        load_frags(0, abase, bbase, 0);
        #pragma unroll
        for (int kk = 0; kk < 4; kk++) {
            if (kk < 3) load_frags(kk + 1, abase, bbase, (kk + 1) & 1);
            do_mma(kk & 1);
        }
        stage = (stage + 1 >= NSTAGE) ? 0 : stage + 1;
    }

    // ---------- epilogue: bias + store ----------
    const int qm = lane >> 2;            // 0..7
    const int qn = (lane & 3) * 2;       // 0,2,4,6
    #pragma unroll
    for (int j = 0; j < 4; j++) {
        int n0 = n_base + warp_n + j * 8 + qn;
        float2 bv = *reinterpret_cast<const float2*>(bias + n0);
        #pragma unroll
        for (int i = 0; i < 4; i++) {
            int m0 = m_base + warp_m + i * 16 + qm;
            float2 v0 = { acc[i][j][0] + bv.x, acc[i][j][1] + bv.y };
            float2 v1 = { acc[i][j][2] + bv.x, acc[i][j][3] + bv.y };
            *reinterpret_cast<float2*>(out + (size_t)m0 * NDIM + n0) = v0;
            *reinterpret_cast<float2*>(out + (size_t)(m0 + 8) * NDIM + n0) = v1;
        }
    }
}

// ============================================================
// Launch
// ============================================================
extern "C" void kernel_launch(void* const* d_in, const int* in_sizes, int n_in,
                              void* d_out, int out_size) {
    const float* x     = (const float*)d_in[0];
    const int*   wq    = (const int*)d_in[1];
    const float* scale = (const float*)d_in[2];
    const float* zp    = (const float*)d_in[3];
    const float* bias  = (const float*)d_in[4];
    float* out = (float*)d_out;

    dequant_kernel<<<(size_t)NDIM * KDIM / 8 / 256, 256>>>(wq, scale, zp);
    xconv_kernel<<<(size_t)MDIM * KDIM / 8 / 256, 256>>>(x);

    static bool attr_set = false;
    if (!attr_set) {
        cudaFuncSetAttribute(gemm_kernel, cudaFuncAttributeMaxDynamicSharedMemorySize, SMEM_BYTES);
        attr_set = true;
    }
    dim3 grid(NDIM / TILE_N, MDIM / TILE_M);   // (32, 64)
    gemm_kernel<<<grid, 256, SMEM_BYTES>>>(bias, out);
}

// round 4
// speedup vs baseline: 1.8004x; 1.3405x over previous
#include <cuda_runtime.h>
#include <cuda_fp16.h>
#include <cstdint>

// ============================================================
// Problem dims (fixed)
// ============================================================
#define MDIM 8192     // B*S
#define NDIM 4096
#define KDIM 4096
#define NGROUPS 64    // group size 64

// Scratch: half-precision copies (sanctioned __device__ globals)
__device__ __half g_Wh[(size_t)NDIM * KDIM];   // 32 MB
__device__ __half g_Xh[(size_t)MDIM * KDIM];   // 64 MB

// ============================================================
// Pass 1 (merged): dequantize W -> half  AND  convert x -> half
// ============================================================
constexpr int W_BLOCKS = (int)((size_t)NDIM * KDIM / 8 / 256);   // 8192
constexpr int X_BLOCKS = (int)((size_t)MDIM * KDIM / 8 / 256);   // 16384

__global__ void __launch_bounds__(256) convert_kernel(
    const int* __restrict__ q, const float* __restrict__ scale, const float* __restrict__ zp,
    const float* __restrict__ x)
{
    if (blockIdx.x < W_BLOCKS) {
        int idx = blockIdx.x * 256 + threadIdx.x;            // 8 elements per thread
        int n = idx >> 9;                                    // K/8 = 512 per row
        int k = (idx & 511) << 3;
        int g = k >> 6;
        float s = scale[n * NGROUPS + g];
        float z = zp[n * NGROUPS + g];
        int4 q0 = reinterpret_cast<const int4*>(q)[idx * 2 + 0];
        int4 q1 = reinterpret_cast<const int4*>(q)[idx * 2 + 1];
        __half2 h[4];
        h[0] = __floats2half2_rn(((float)q0.x - z) * s, ((float)q0.y - z) * s);
        h[1] = __floats2half2_rn(((float)q0.z - z) * s, ((float)q0.w - z) * s);
        h[2] = __floats2half2_rn(((float)q1.x - z) * s, ((float)q1.y - z) * s);
        h[3] = __floats2half2_rn(((float)q1.z - z) * s, ((float)q1.w - z) * s);
        reinterpret_cast<uint4*>(g_Wh)[idx] = *reinterpret_cast<uint4*>(h);
    } else {
        int idx = (blockIdx.x - W_BLOCKS) * 256 + threadIdx.x;
        float4 a = reinterpret_cast<const float4*>(x)[idx * 2 + 0];
        float4 b = reinterpret_cast<const float4*>(x)[idx * 2 + 1];
        __half2 h[4];
        h[0] = __floats2half2_rn(a.x, a.y);
        h[1] = __floats2half2_rn(a.z, a.w);
        h[2] = __floats2half2_rn(b.x, b.y);
        h[3] = __floats2half2_rn(b.z, b.w);
        reinterpret_cast<uint4*>(g_Xh)[idx] = *reinterpret_cast<uint4*>(h);
    }
}

// ============================================================
// Pass 2: GEMM  out[M,N] = Xh @ Wh^T + bias   (fp16 in, fp32 acc)
// CTA 128x128, 8 warps (warp 64x32), KS=64, 3 stages, 2 CTAs/SM.
// LDSM interleaved between MMAs; cp.async spread across k16 steps.
// ============================================================
constexpr int TILE_M = 128;
constexpr int TILE_N = 128;
constexpr int KS = 64;
constexpr int NSTAGE = 3;
constexpr int NKS = KDIM / KS;                  // 64
constexpr int A_STAGE_B = TILE_M * 128;         // 16 KB
constexpr int B_STAGE_B = TILE_N * 128;         // 16 KB
constexpr int STAGE_B = A_STAGE_B + B_STAGE_B;  // 32 KB
constexpr int SMEM_BYTES = NSTAGE * STAGE_B;    // 96 KB

__device__ __forceinline__ uint32_t smem_u32(const void* p) {
    uint32_t a;
    asm("{ .reg .u64 t; cvta.to.shared.u64 t, %1; cvt.u32.u64 %0, t; }" : "=r"(a) : "l"(p));
    return a;
}
__device__ __forceinline__ void cp_async16(uint32_t dst, const void* src) {
    asm volatile("cp.async.cg.shared.global [%0], [%1], 16;" :: "r"(dst), "l"(src));
}
__device__ __forceinline__ void cp_commit() {
    asm volatile("cp.async.commit_group;" ::: "memory");
}
template <int N>
__device__ __forceinline__ void cp_wait() {
    asm volatile("cp.async.wait_group %0;" :: "n"(N) : "memory");
}
__device__ __forceinline__ void ldmatrix_x4(uint32_t& r0, uint32_t& r1, uint32_t& r2, uint32_t& r3,
                                            uint32_t addr) {
    asm volatile("ldmatrix.sync.aligned.m8n8.x4.shared.b16 {%0,%1,%2,%3}, [%4];"
                 : "=r"(r0), "=r"(r1), "=r"(r2), "=r"(r3) : "r"(addr));
}
__device__ __forceinline__ void mma16816(float* c, const uint32_t* a, uint32_t b0, uint32_t b1) {
    asm volatile(
        "mma.sync.aligned.m16n8k16.row.col.f32.f16.f16.f32 "
        "{%0,%1,%2,%3}, {%4,%5,%6,%7}, {%8,%9}, {%0,%1,%2,%3};"
        : "+f"(c[0]), "+f"(c[1]), "+f"(c[2]), "+f"(c[3])
        : "r"(a[0]), "r"(a[1]), "r"(a[2]), "r"(a[3]), "r"(b0), "r"(b1));
}

__global__ void __launch_bounds__(256, 2) gemm_kernel(
    const float* __restrict__ bias, float* __restrict__ out)
{
    extern __shared__ __align__(1024) char smem[];
    const uint32_t sb = smem_u32(smem);
    const int tid = threadIdx.x;
    const int wid = tid >> 5;
    const int lane = tid & 31;

    const int m_base = blockIdx.y * TILE_M;
    const int n_base = blockIdx.x * TILE_N;
    const int warp_m = (wid >> 2) * 64;   // 2 warps along M
    const int warp_n = (wid & 3) * 32;    // 4 warps along N

    // ---------- cp.async addressing ----------
    // 8 x 16B chunks per thread per stage: first 4 -> A, last 4 -> B.
    const int row = tid >> 1;
    const int cs = (tid & 1) * 4;
    const __half* gA = g_Xh + (size_t)(m_base + row) * KDIM + cs * 8;
    const __half* gB = g_Wh + (size_t)(n_base + row) * KDIM + cs * 8;

    uint32_t cpDst[8];
    const __half* cpSrc[8];
    #pragma unroll
    for (int c = 0; c < 4; c++) {
        uint32_t off = row * 128 + (((cs + c) ^ (row & 7)) * 16);
        cpDst[c] = off;                 cpSrc[c] = gA + c * 8;
        cpDst[4 + c] = A_STAGE_B + off; cpSrc[4 + c] = gB + c * 8;
    }

    auto issue_full_stage = [&](int ks, int stage) {
        uint32_t base = sb + stage * STAGE_B;
        #pragma unroll
        for (int c = 0; c < 8; c++) cp_async16(base + cpDst[c], cpSrc[c] + ks * KS);
    };

    issue_full_stage(0, 0); cp_commit();
    issue_full_stage(1, 1); cp_commit();

    float acc[4][4][4];
    #pragma unroll
    for (int i = 0; i < 4; i++)
        #pragma unroll
        for (int j = 0; j < 4; j++)
            #pragma unroll
            for (int r = 0; r < 4; r++) acc[i][j][r] = 0.f;

    // ldmatrix lane addressing
    const int lrow = lane & 15;
    const int lhc = lane >> 4;           // hi/lo 16B chunk within k16
    const int lsw = lrow & 7;

    uint32_t af[2][4][4], bf[2][2][4];   // double-buffered fragments

    int stage = 0;
    for (int ks = 0; ks < NKS; ks++) {
        cp_wait<1>();
        __syncthreads();

        const uint32_t abase = sb + stage * STAGE_B;
        const uint32_t bbase = abase + A_STAGE_B;
        const bool pref = (ks + 2 < NKS);
        const int pstage = (stage + 2 >= NSTAGE) ? stage + 2 - NSTAGE : stage + 2;
        const uint32_t pbase = sb + pstage * STAGE_B;
        const int pks = (ks + 2) * KS;

        // kk=0 fragment burst (buf 0)
        {
            const uint32_t coff = (uint32_t)(((0 + lhc) ^ lsw) * 16) + ((0 >> 1) * 0);
            const uint32_t c0 = (uint32_t)(((2 * 0 + lhc) ^ lsw) * 16);
            #pragma unroll
            for (int i = 0; i < 4; i++)
                ldmatrix_x4(af[0][i][0], af[0][i][1], af[0][i][2], af[0][i][3],
                            abase + (warp_m + i * 16 + lrow) * 128 + c0);
            #pragma unroll
            for (int j = 0; j < 2; j++)
                ldmatrix_x4(bf[0][j][0], bf[0][j][1], bf[0][j][2], bf[0][j][3],
                            bbase + (warp_n + j * 16 + lrow) * 128 + c0);
            (void)coff;
        }

        #pragma unroll
        for (int kk = 0; kk < 4; kk++) {
            const int mb = kk & 1;
            const int lb = (kk + 1) & 1;
            const bool doload = (kk < 3);
            const uint32_t coff = (uint32_t)(((2 * (kk + 1) + lhc) ^ lsw) * 16);

            // 2 cp.async for stage+2, spread across kk
            if (pref) {
                cp_async16(pbase + cpDst[2 * kk + 0], cpSrc[2 * kk + 0] + pks);
                cp_async16(pbase + cpDst[2 * kk + 1], cpSrc[2 * kk + 1] + pks);
            }

            // interleaved: LDSM(kk+1) sandwiched between MMA(kk) pairs
            if (doload)
                ldmatrix_x4(af[lb][0][0], af[lb][0][1], af[lb][0][2], af[lb][0][3],
                            abase + (warp_m + 0 * 16 + lrow) * 128 + coff);
            mma16816(acc[0][0], af[mb][0], bf[mb][0][0], bf[mb][0][2]);
            mma16816(acc[0][1], af[mb][0], bf[mb][0][1], bf[mb][0][3]);
            if (doload)
                ldmatrix_x4(af[lb][1][0], af[lb][1][1], af[lb][1][2], af[lb][1][3],
                            abase + (warp_m + 1 * 16 + lrow) * 128 + coff);
            mma16816(acc[0][2], af[mb][0], bf[mb][1][0], bf[mb][1][2]);
            mma16816(acc[0][3], af[mb][0], bf[mb][1][1], bf[mb][1][3]);
            if (doload)
                ldmatrix_x4(af[lb][2][0], af[lb][2][1], af[lb][2][2], af[lb][2][3],
                            abase + (warp_m + 2 * 16 + lrow) * 128 + coff);
            mma16816(acc[1][0], af[mb][1], bf[mb][0][0], bf[mb][0][2]);
            mma16816(acc[1][1], af[mb][1], bf[mb][0][1], bf[mb][0][3]);
            if (doload)
                ldmatrix_x4(af[lb][3][0], af[lb][3][1], af[lb][3][2], af[lb][3][3],
                            abase + (warp_m + 3 * 16 + lrow) * 128 + coff);
            mma16816(acc[1][2], af[mb][1], bf[mb][1][0], bf[mb][1][2]);
            mma16816(acc[1][3], af[mb][1], bf[mb][1][1], bf[mb][1][3]);
            if (doload)
                ldmatrix_x4(bf[lb][0][0], bf[lb][0][1], bf[lb][0][2], bf[lb][0][3],
                            bbase + (warp_n + 0 * 16 + lrow) * 128 + coff);
            mma16816(acc[2][0], af[mb][2], bf[mb][0][0], bf[mb][0][2]);
            mma16816(acc[2][1], af[mb][2], bf[mb][0][1], bf[mb][0][3]);
            if (doload)
                ldmatrix_x4(bf[lb][1][0], bf[lb][1][1], bf[lb][1][2], bf[lb][1][3],
                            bbase + (warp_n + 1 * 16 + lrow) * 128 + coff);
            mma16816(acc[2][2], af[mb][2], bf[mb][1][0], bf[mb][1][2]);
            mma16816(acc[2][3], af[mb][2], bf[mb][1][1], bf[mb][1][3]);
            mma16816(acc[3][0], af[mb][3], bf[mb][0][0], bf[mb][0][2]);
            mma16816(acc[3][1], af[mb][3], bf[mb][0][1], bf[mb][0][3]);
            mma16816(acc[3][2], af[mb][3], bf[mb][1][0], bf[mb][1][2]);
            mma16816(acc[3][3], af[mb][3], bf[mb][1][1], bf[mb][1][3]);

            if (kk == 3) cp_commit();
        }
        stage = (stage + 1 >= NSTAGE) ? 0 : stage + 1;
    }

    // ---------- epilogue: bias + store ----------
    const int qm = lane >> 2;            // 0..7
    const int qn = (lane & 3) * 2;       // 0,2,4,6
    #pragma unroll
    for (int j = 0; j < 4; j++) {
        int n0 = n_base + warp_n + j * 8 + qn;
        float2 bv = *reinterpret_cast<const float2*>(bias + n0);
        #pragma unroll
        for (int i = 0; i < 4; i++) {
            int m0 = m_base + warp_m + i * 16 + qm;
            float2 v0 = { acc[i][j][0] + bv.x, acc[i][j][1] + bv.y };
            float2 v1 = { acc[i][j][2] + bv.x, acc[i][j][3] + bv.y };
            *reinterpret_cast<float2*>(out + (size_t)m0 * NDIM + n0) = v0;
            *reinterpret_cast<float2*>(out + (size_t)(m0 + 8) * NDIM + n0) = v1;
        }
    }
}

// ============================================================
// Launch
// ============================================================
extern "C" void kernel_launch(void* const* d_in, const int* in_sizes, int n_in,
                              void* d_out, int out_size) {
    const float* x     = (const float*)d_in[0];
    const int*   wq    = (const int*)d_in[1];
    const float* scale = (const float*)d_in[2];
    const float* zp    = (const float*)d_in[3];
    const float* bias  = (const float*)d_in[4];
    float* out = (float*)d_out;

    convert_kernel<<<W_BLOCKS + X_BLOCKS, 256>>>(wq, scale, zp, x);

    static bool attr_set = false;
    if (!attr_set) {
        cudaFuncSetAttribute(gemm_kernel, cudaFuncAttributeMaxDynamicSharedMemorySize, SMEM_BYTES);
        attr_set = true;
    }
    dim3 grid(NDIM / TILE_N, MDIM / TILE_M);   // (32, 64)
    gemm_kernel<<<grid, 256, SMEM_BYTES>>>(bias, out);
}